// round 1
// baseline (speedup 1.0000x reference)
#include <cuda_runtime.h>
#include <cstdint>

#define T_STEPS 512
#define BATCH   128
#define IDIM    512
#define HDIM    512
#define BH      (BATCH * HDIM)   /* 65536 */

// per-batch-group arrival counters (16 groups of 8 CTAs)
__device__ int g_cnt[16];

__device__ __forceinline__ unsigned f2tf32(float f) {
    unsigned u;
    asm("cvt.rna.tf32.f32 %0, %1;" : "=r"(u) : "f"(f));
    return u;
}
__device__ __forceinline__ float tf32f(float f) { return __uint_as_float(f2tf32(f)); }

__device__ __forceinline__ void mma_tf32(float c[4], const unsigned a[4],
                                         unsigned b0, unsigned b1) {
    asm volatile(
        "mma.sync.aligned.m16n8k8.row.col.f32.tf32.tf32.f32 "
        "{%0,%1,%2,%3}, {%4,%5,%6,%7}, {%8,%9}, {%0,%1,%2,%3};"
        : "+f"(c[0]), "+f"(c[1]), "+f"(c[2]), "+f"(c[3])
        : "r"(a[0]), "r"(a[1]), "r"(a[2]), "r"(a[3]), "r"(b0), "r"(b1));
}

// ============================================================================
// Kernel 1: xw[t,b,:] = x[t,b,:] @ W_ih^T + bias   (M=65536, N=512, K=512)
// Tile 128x64, BK=16, 8 warps (warp tile 32x32), tf32 mma, fp32 accum.
// Also zeroes the group counters (block 0) so each graph replay is clean.
// ============================================================================
__global__ __launch_bounds__(256) void xw_gemm(const float* __restrict__ x,
                                               const float* __restrict__ w_ih,
                                               const float* __restrict__ bias,
                                               float* __restrict__ out) {
    if (blockIdx.x == 0 && threadIdx.x < 16) g_cnt[threadIdx.x] = 0;

    __shared__ __align__(16) float Xs[128][20];  // pitch 20 -> conflict-free frags
    __shared__ __align__(16) float Ws[64][20];

    const int tid  = threadIdx.x;
    const int warp = tid >> 5, lane = tid & 31;
    const int g = lane >> 2, tg = lane & 3;

    const int nt = blockIdx.x & 7;        // 8 n-tiles of 64
    const int mt = blockIdx.x >> 3;       // 512 m-tiles of 128
    const int m0 = mt * 128, n0 = nt * 64;
    const int wm = warp >> 1, wn = warp & 1;  // 4x2 warp grid

    float c[2][4][4];
#pragma unroll
    for (int i = 0; i < 2; i++)
#pragma unroll
        for (int nb = 0; nb < 4; nb++)
#pragma unroll
            for (int r = 0; r < 4; r++) c[i][nb][r] = 0.f;

    const int xr = tid >> 2, xc = (tid & 3) * 4;

    for (int kt = 0; kt < IDIM; kt += 16) {
        float4 v0 = *(const float4*)(x + (size_t)(m0 + xr) * IDIM + kt + xc);
        float4 v1 = *(const float4*)(x + (size_t)(m0 + xr + 64) * IDIM + kt + xc);
        float4 wv = *(const float4*)(w_ih + (size_t)(n0 + xr) * IDIM + kt + xc);

        *(float4*)&Xs[xr][xc]      = make_float4(tf32f(v0.x), tf32f(v0.y), tf32f(v0.z), tf32f(v0.w));
        *(float4*)&Xs[xr + 64][xc] = make_float4(tf32f(v1.x), tf32f(v1.y), tf32f(v1.z), tf32f(v1.w));
        if (xr < 64)
            *(float4*)&Ws[xr][xc]  = make_float4(tf32f(wv.x), tf32f(wv.y), tf32f(wv.z), tf32f(wv.w));
        __syncthreads();

#pragma unroll
        for (int k8 = 0; k8 < 2; k8++) {
            unsigned a[2][4];
#pragma unroll
            for (int i = 0; i < 2; i++) {
                int row = wm * 32 + i * 16 + g;
                int col = k8 * 8 + tg;
                a[i][0] = __float_as_uint(Xs[row][col]);
                a[i][1] = __float_as_uint(Xs[row + 8][col]);
                a[i][2] = __float_as_uint(Xs[row][col + 4]);
                a[i][3] = __float_as_uint(Xs[row + 8][col + 4]);
            }
            unsigned bf[4][2];
#pragma unroll
            for (int nb = 0; nb < 4; nb++) {
                int row = wn * 32 + nb * 8 + g;
                int col = k8 * 8 + tg;
                bf[nb][0] = __float_as_uint(Ws[row][col]);
                bf[nb][1] = __float_as_uint(Ws[row][col + 4]);
            }
#pragma unroll
            for (int i = 0; i < 2; i++)
#pragma unroll
                for (int nb = 0; nb < 4; nb++)
                    mma_tf32(c[i][nb], a[i], bf[nb][0], bf[nb][1]);
        }
        __syncthreads();
    }

#pragma unroll
    for (int i = 0; i < 2; i++)
#pragma unroll
        for (int nb = 0; nb < 4; nb++) {
            int row = m0 + wm * 32 + i * 16 + g;
            int col = n0 + wn * 32 + nb * 8 + tg * 2;
            float b0v = bias[col], b1v = bias[col + 1];
            out[(size_t)row * HDIM + col]           = c[i][nb][0] + b0v;
            out[(size_t)row * HDIM + col + 1]       = c[i][nb][1] + b1v;
            out[(size_t)(row + 8) * HDIM + col]     = c[i][nb][2] + b0v;
            out[(size_t)(row + 8) * HDIM + col + 1] = c[i][nb][3] + b1v;
        }
}

// ============================================================================
// Kernel 2: persistent recurrence. 128 CTAs = 8 n-slices x 16 batch groups.
// CTA (j,i): batch rows j*8..j*8+7, h columns i*64..i*64+63, full K=512.
// W_hh slice lives in REGISTERS as tf32 A-fragments (128 regs/thread).
// Step MMA: D[n,m] = W . h^T  (W as A so M=8 batch == n8 exactly, no padding).
// Warps split K 8-way; partials reduced via SMEM; tanh; write in-place to out.
// Per-group 8-CTA barrier via g_cnt[j] with release/acquire fencing.
// ============================================================================
__global__ __launch_bounds__(256) void rnn_step_kernel(const float* __restrict__ w_hh,
                                                       float* __restrict__ out) {
    __shared__ __align__(16) float Hs[8][516];   // h tile (tf32 bits), pad 516
    __shared__ __align__(16) float Red[8][512];  // per-warp partial sums

    const int tid  = threadIdx.x;
    const int warp = tid >> 5, lane = tid & 31;
    const int g = lane >> 2, tg = lane & 3;
    const int j = blockIdx.x >> 3;  // batch group 0..15
    const int i = blockIdx.x & 7;   // n slice 0..7

    // ---- preload W_hh slice into registers as tf32 A-fragments ----
    unsigned aw[4][8][4];
#pragma unroll
    for (int nb = 0; nb < 4; nb++)
#pragma unroll
        for (int k8 = 0; k8 < 8; k8++) {
            int row = i * 64 + nb * 16 + g;
            int col = warp * 64 + k8 * 8 + tg;
            aw[nb][k8][0] = f2tf32(w_hh[(size_t)row * HDIM + col]);
            aw[nb][k8][1] = f2tf32(w_hh[(size_t)(row + 8) * HDIM + col]);
            aw[nb][k8][2] = f2tf32(w_hh[(size_t)row * HDIM + col + 4]);
            aw[nb][k8][3] = f2tf32(w_hh[(size_t)(row + 8) * HDIM + col + 4]);
        }

    // ---- my two output slots (fixed across steps): slot s = reg*32 + lane' ----
    int offA, offB;
    {
        int s[2] = { tid * 2, tid * 2 + 1 };
        int off[2];
#pragma unroll
        for (int q = 0; q < 2; q++) {
            int reg = s[q] >> 5, ln = s[q] & 31;
            int nb = reg >> 2, cr = reg & 3;
            int gg = ln >> 2, tt = ln & 3;
            int n = i * 64 + nb * 16 + gg + ((cr & 2) << 2);  // +8 if cr>=2
            int m = j * 8 + tt * 2 + (cr & 1);
            off[q] = m * HDIM + n;
        }
        offA = off[0]; offB = off[1];
    }

    const float* hbase = out + (size_t)j * 8 * HDIM;  // + (t-1)*BH at use
    const int wk = warp * 64;

    for (int t = 0; t < T_STEPS; t++) {
        // prefetch xw for my slots (independent of the barrier)
        float xw0 = out[(size_t)t * BH + offA];
        float xw1 = out[(size_t)t * BH + offB];

        // ---- wait for all 8 CTAs of group j to finish step t-1 ----
        if (t > 0) {
            if (tid == 0) {
                while (*(volatile int*)&g_cnt[j] < 8 * t) { }
                __threadfence();  // acquire
            }
        }
        __syncthreads();

        // ---- stage h_{t-1} (tf32-rounded) into SMEM ----
        if (t == 0) {
#pragma unroll
            for (int u = 0; u < 4; u++) {
                int e = tid * 16 + u * 4;
                *(float4*)&Hs[e >> 9][e & 511] = make_float4(0.f, 0.f, 0.f, 0.f);
            }
        } else {
            const float* hsrc = hbase + (size_t)(t - 1) * BH;
#pragma unroll
            for (int u = 0; u < 4; u++) {
                int e = tid * 16 + u * 4;
                float4 v = *(const float4*)(hsrc + e);  // 8 consecutive rows of H
                *(float4*)&Hs[e >> 9][e & 511] =
                    make_float4(tf32f(v.x), tf32f(v.y), tf32f(v.z), tf32f(v.w));
            }
        }
        __syncthreads();

        // ---- D += W_slice(k-range) . h^T ----
        float c[4][4] = {{0.f}};
#pragma unroll
        for (int k8 = 0; k8 < 8; k8++) {
            unsigned b0 = __float_as_uint(Hs[g][wk + k8 * 8 + tg]);
            unsigned b1 = __float_as_uint(Hs[g][wk + k8 * 8 + tg + 4]);
#pragma unroll
            for (int nb = 0; nb < 4; nb++)
                mma_tf32(c[nb], aw[nb][k8], b0, b1);
        }

        // ---- cross-warp K reduction via SMEM ----
#pragma unroll
        for (int nb = 0; nb < 4; nb++)
#pragma unroll
            for (int cr = 0; cr < 4; cr++)
                Red[warp][(nb * 4 + cr) * 32 + lane] = c[nb][cr];
        __syncthreads();

        float s0 = 0.f, s1 = 0.f;
#pragma unroll
        for (int w = 0; w < 8; w++) {
            float2 v = *(const float2*)&Red[w][tid * 2];
            s0 += v.x; s1 += v.y;
        }
        float r0 = tanhf(xw0 + s0);
        float r1 = tanhf(xw1 + s1);
        out[(size_t)t * BH + offA] = r0;
        out[(size_t)t * BH + offB] = r1;
        if (t == T_STEPS - 1) {   // h_final appended after outputs
            out[(size_t)T_STEPS * BH + offA] = r0;
            out[(size_t)T_STEPS * BH + offB] = r1;
        }

        // ---- release + arrive ----
        __threadfence();
        __syncthreads();
        if (tid == 0) atomicAdd(&g_cnt[j], 1);
    }
}

extern "C" void kernel_launch(void* const* d_in, const int* in_sizes, int n_in,
                              void* d_out, int out_size) {
    (void)in_sizes; (void)n_in; (void)out_size;
    const float* x    = (const float*)d_in[0];
    const float* w_ih = (const float*)d_in[1];
    const float* w_hh = (const float*)d_in[2];
    const float* b    = (const float*)d_in[3];
    float* out = (float*)d_out;

    // xw = x @ W_ih^T + b  -> written into out[0 : T*B*H) (in-place workspace)
    xw_gemm<<<4096, 256>>>(x, w_ih, b, out);
    // sequential recurrence, persistent kernel (128 CTAs, all co-resident)
    rnn_step_kernel<<<128, 256>>>(w_hh, out);
}

// round 2
// speedup vs baseline: 1.1080x; 1.1080x over previous
#include <cuda_runtime.h>
#include <cstdint>

#define T_STEPS 512
#define BATCH   128
#define IDIM    512
#define HDIM    512
#define BH      (BATCH * HDIM)   /* 65536 */

__device__ __forceinline__ unsigned f2tf32(float f) {
    unsigned u;
    asm("cvt.rna.tf32.f32 %0, %1;" : "=r"(u) : "f"(f));
    return u;
}

__device__ __forceinline__ void mma_tf32(float c[4], const unsigned a[4],
                                         unsigned b0, unsigned b1) {
    asm volatile(
        "mma.sync.aligned.m16n8k8.row.col.f32.tf32.tf32.f32 "
        "{%0,%1,%2,%3}, {%4,%5,%6,%7}, {%8,%9}, {%0,%1,%2,%3};"
        : "+f"(c[0]), "+f"(c[1]), "+f"(c[2]), "+f"(c[3])
        : "r"(a[0]), "r"(a[1]), "r"(a[2]), "r"(a[3]), "r"(b0), "r"(b1));
}

__device__ __forceinline__ uint32_t smem_u32(const void* p) {
    return (uint32_t)__cvta_generic_to_shared(p);
}
__device__ __forceinline__ void cp16(uint32_t dst, const void* src) {
    asm volatile("cp.async.cg.shared.global [%0], [%1], 16;" :: "r"(dst), "l"(src));
}
__device__ __forceinline__ uint32_t mapa_rank(uint32_t addr, uint32_t rank) {
    uint32_t r;
    asm("mapa.shared::cluster.u32 %0, %1, %2;" : "=r"(r) : "r"(addr), "r"(rank));
    return r;
}
__device__ __forceinline__ void st_cluster_u64(uint32_t addr, uint64_t v) {
    asm volatile("st.shared::cluster.u64 [%0], %1;" :: "r"(addr), "l"(v) : "memory");
}

// ============================================================================
// Kernel 1: xw[t,b,:] = x[t,b,:] @ W_ih^T + bias   (M=65536, N=512, K=512)
// Tile 128x64, BK=16, 8 warps (warp tile 32x32), tf32 mma, fp32 accum.
// cp.async double-buffered; tf32 rounding done at fragment-load time.
// ============================================================================
__global__ __launch_bounds__(256) void xw_gemm(const float* __restrict__ x,
                                               const float* __restrict__ w_ih,
                                               const float* __restrict__ bias,
                                               float* __restrict__ out) {
    __shared__ __align__(16) float Xs[2][128][20];  // pitch 20 -> conflict-free frags
    __shared__ __align__(16) float Ws[2][64][20];

    const int tid  = threadIdx.x;
    const int warp = tid >> 5, lane = tid & 31;
    const int g = lane >> 2, tg = lane & 3;

    const int nt = blockIdx.x & 7;        // 8 n-tiles of 64
    const int mt = blockIdx.x >> 3;       // 512 m-tiles of 128
    const int m0 = mt * 128, n0 = nt * 64;
    const int wm = warp >> 1, wn = warp & 1;  // 4x2 warp grid

    float c[2][4][4];
#pragma unroll
    for (int i = 0; i < 2; i++)
#pragma unroll
        for (int nb = 0; nb < 4; nb++)
#pragma unroll
            for (int r = 0; r < 4; r++) c[i][nb][r] = 0.f;

    const int xr = tid >> 2, xc = (tid & 3) * 4;
    const float* xs0  = x    + (size_t)(m0 + xr) * IDIM + xc;
    const float* xs1  = x    + (size_t)(m0 + xr + 64) * IDIM + xc;
    const float* wsrc = w_ih + (size_t)(n0 + xr) * IDIM + xc;

    const uint32_t dX0[2] = { smem_u32(&Xs[0][xr][xc]),      smem_u32(&Xs[1][xr][xc]) };
    const uint32_t dX1[2] = { smem_u32(&Xs[0][xr + 64][xc]), smem_u32(&Xs[1][xr + 64][xc]) };
    const uint32_t dW[2]  = { smem_u32(&Ws[0][xr][xc]),      smem_u32(&Ws[1][xr][xc]) };

    // prologue: stage 0
    cp16(dX0[0], xs0);
    cp16(dX1[0], xs1);
    if (xr < 64) cp16(dW[0], wsrc);
    asm volatile("cp.async.commit_group;");

    for (int it = 0; it < 32; ++it) {
        const int s = it & 1;
        if (it < 31) {
            const int kt = (it + 1) * 16;
            cp16(dX0[s ^ 1], xs0 + kt);
            cp16(dX1[s ^ 1], xs1 + kt);
            if (xr < 64) cp16(dW[s ^ 1], wsrc + kt);
            asm volatile("cp.async.commit_group;");
            asm volatile("cp.async.wait_group 1;");
        } else {
            asm volatile("cp.async.wait_group 0;");
        }
        __syncthreads();

#pragma unroll
        for (int k8 = 0; k8 < 2; k8++) {
            const int col = k8 * 8 + tg;
            unsigned a[2][4];
#pragma unroll
            for (int i = 0; i < 2; i++) {
                int row = wm * 32 + i * 16 + g;
                a[i][0] = f2tf32(Xs[s][row][col]);
                a[i][1] = f2tf32(Xs[s][row + 8][col]);
                a[i][2] = f2tf32(Xs[s][row][col + 4]);
                a[i][3] = f2tf32(Xs[s][row + 8][col + 4]);
            }
            unsigned bf[4][2];
#pragma unroll
            for (int nb = 0; nb < 4; nb++) {
                int row = wn * 32 + nb * 8 + g;
                bf[nb][0] = f2tf32(Ws[s][row][col]);
                bf[nb][1] = f2tf32(Ws[s][row][col + 4]);
            }
#pragma unroll
            for (int i = 0; i < 2; i++)
#pragma unroll
                for (int nb = 0; nb < 4; nb++)
                    mma_tf32(c[i][nb], a[i], bf[nb][0], bf[nb][1]);
        }
        __syncthreads();
    }

#pragma unroll
    for (int i = 0; i < 2; i++)
#pragma unroll
        for (int nb = 0; nb < 4; nb++) {
            int row = m0 + wm * 32 + i * 16 + g;
            int col = n0 + wn * 32 + nb * 8 + tg * 2;
            float b0v = bias[col], b1v = bias[col + 1];
            out[(size_t)row * HDIM + col]           = c[i][nb][0] + b0v;
            out[(size_t)row * HDIM + col + 1]       = c[i][nb][1] + b1v;
            out[(size_t)(row + 8) * HDIM + col]     = c[i][nb][2] + b0v;
            out[(size_t)(row + 8) * HDIM + col + 1] = c[i][nb][3] + b1v;
        }
}

// ============================================================================
// Kernel 2: persistent recurrence with 8-CTA clusters + DSMEM h exchange.
// Cluster = batch group j (blockIdx.x>>3); rank i = n-slice (blockIdx.x&7).
// CTA (j,i): batch rows j*8..j*8+7, h columns i*64..i*64+63, full K=512.
// W_hh slice in registers as tf32 A-fragments (128 regs/thread).
// Per step: MMA from local Hs replica -> 2-phase cross-warp reduce -> tanh ->
// broadcast slice to all 8 peers' Hs (st.shared::cluster.u64, double-buffered)
// -> barrier.cluster.arrive (release) ... next step wait (acquire).
// ============================================================================
__global__ __launch_bounds__(256) __cluster_dims__(8, 1, 1)
void rnn_step_kernel(const float* __restrict__ w_hh, float* __restrict__ out) {
    __shared__ __align__(16) float Hs[2][8][516];   // full h replica, tf32 bits
    __shared__ __align__(16) float Red[4][544];     // pitch 68 -> conflict-free

    const int tid  = threadIdx.x;
    const int warp = tid >> 5, lane = tid & 31;
    const int g = lane >> 2, tg = lane & 3;
    const int j = blockIdx.x >> 3;  // batch group 0..15
    const int i = blockIdx.x & 7;   // n slice 0..7 (== cluster rank)

    // ---- preload W_hh slice into registers as tf32 A-fragments ----
    unsigned aw[4][8][4];
#pragma unroll
    for (int nb = 0; nb < 4; nb++)
#pragma unroll
        for (int k8 = 0; k8 < 8; k8++) {
            int row = i * 64 + nb * 16 + g;
            int col = warp * 64 + k8 * 8 + tg;
            aw[nb][k8][0] = f2tf32(w_hh[(size_t)row * HDIM + col]);
            aw[nb][k8][1] = f2tf32(w_hh[(size_t)(row + 8) * HDIM + col]);
            aw[nb][k8][2] = f2tf32(w_hh[(size_t)row * HDIM + col + 4]);
            aw[nb][k8][3] = f2tf32(w_hh[(size_t)(row + 8) * HDIM + col + 4]);
        }

    // Linear ownership: thread -> (m = warp, cols n, n+1 = lane*2, lane*2+1)
    const int m = warp;
    const int n = lane * 2;
    const size_t obase = (size_t)(j * 8 + m) * HDIM + i * 64 + n;
    const uint32_t hs_word = (uint32_t)(m * 516 + i * 64 + n);
    const uint32_t hs_addr0 = smem_u32(&Hs[0][0][0]) + hs_word * 4;

    uint32_t raddr[8];
#pragma unroll
    for (int r = 0; r < 8; r++) raddr[r] = mapa_rank(hs_addr0, r);

    const int wk = warp * 64;
    float2 xwv = *(const float2*)(out + obase);  // xw[t=0]

    for (int t = 0; t < T_STEPS; t++) {
        float r0, r1;
        if (t == 0) {
            r0 = tanhf(xwv.x);
            r1 = tanhf(xwv.y);
        } else {
            asm volatile("barrier.cluster.wait.aligned;" ::: "memory");  // h_{t-1} ready
            const float* hb = &Hs[(t + 1) & 1][0][0];  // buffer (t-1)&1

            float c[4][4];
#pragma unroll
            for (int nb = 0; nb < 4; nb++)
#pragma unroll
                for (int r = 0; r < 4; r++) c[nb][r] = 0.f;

#pragma unroll
            for (int k8 = 0; k8 < 8; k8++) {
                unsigned b0 = __float_as_uint(hb[g * 516 + wk + k8 * 8 + tg]);
                unsigned b1 = __float_as_uint(hb[g * 516 + wk + k8 * 8 + tg + 4]);
#pragma unroll
                for (int nb = 0; nb < 4; nb++)
                    mma_tf32(c[nb], aw[nb][k8], b0, b1);
            }

            // ---- 2-phase cross-warp K reduction (fits 48KB static smem) ----
            if (warp >= 4) {
                float* rp = Red[warp - 4];
#pragma unroll
                for (int nb = 0; nb < 4; nb++)
#pragma unroll
                    for (int r = 0; r < 4; r++) {
                        int idx = (tg * 2 + (r & 1)) * 68 + nb * 16 + g + ((r & 2) << 2);
                        rp[idx] = c[nb][r];
                    }
            }
            __syncthreads();
            if (warp < 4) {
                float* rp = Red[warp];
#pragma unroll
                for (int nb = 0; nb < 4; nb++)
#pragma unroll
                    for (int r = 0; r < 4; r++) {
                        int idx = (tg * 2 + (r & 1)) * 68 + nb * 16 + g + ((r & 2) << 2);
                        rp[idx] += c[nb][r];
                    }
            }
            __syncthreads();

            float s0 = 0.f, s1 = 0.f;
#pragma unroll
            for (int w = 0; w < 4; w++) {
                float2 v = *(const float2*)&Red[w][m * 68 + n];
                s0 += v.x;
                s1 += v.y;
            }
            r0 = tanhf(xwv.x + s0);
            r1 = tanhf(xwv.y + s1);
        }

        // ---- broadcast h_t slice to all 8 cluster CTAs (tf32-rounded) ----
        if (t < T_STEPS - 1) {
            uint64_t pv = ((uint64_t)f2tf32(r1) << 32) | (uint64_t)f2tf32(r0);
            const uint32_t boff = (t & 1) ? (8u * 516u * 4u) : 0u;
#pragma unroll
            for (int r = 0; r < 8; r++) st_cluster_u64(raddr[r] + boff, pv);
            asm volatile("barrier.cluster.arrive.aligned;" ::: "memory");  // release
        }

        // ---- global output (full fp32) + next-step xw prefetch ----
        *(float2*)(out + (size_t)t * BH + obase) = make_float2(r0, r1);
        if (t == T_STEPS - 1) {
            *(float2*)(out + (size_t)T_STEPS * BH + obase) = make_float2(r0, r1);
        } else {
            xwv = *(const float2*)(out + (size_t)(t + 1) * BH + obase);
        }
    }
}

extern "C" void kernel_launch(void* const* d_in, const int* in_sizes, int n_in,
                              void* d_out, int out_size) {
    (void)in_sizes; (void)n_in; (void)out_size;
    const float* x    = (const float*)d_in[0];
    const float* w_ih = (const float*)d_in[1];
    const float* w_hh = (const float*)d_in[2];
    const float* b    = (const float*)d_in[3];
    float* out = (float*)d_out;

    // xw = x @ W_ih^T + b  -> written into out[0 : T*B*H) (in-place workspace)
    xw_gemm<<<4096, 256>>>(x, w_ih, b, out);
    // sequential recurrence: 16 clusters of 8 CTAs, all co-resident
    rnn_step_kernel<<<128, 256>>>(w_hh, out);
}